// round 15
// baseline (speedup 1.0000x reference)
#include <cuda_runtime.h>
#include <cuda_fp16.h>
#include <cstdint>
#include <math.h>

#define Nn 50000
#define Ee 800000
#define Dd 128

#define TABN 32768
#define TH0  (-1000.0f)
#define HSTEP   (2000.0f / (TABN - 1))
#define TSCALE  ((TABN - 1) / 2000.0f)

// ---------------- scratch (static device globals; no allocation) ----------------
__device__ __half g_xh[(size_t)Nn * Dd];
__device__ __half g_qh[(size_t)Nn * Dd];
__device__ __half g_kh[(size_t)Nn * Dd];
__device__ __half g_vh[(size_t)Nn * Dd];
__device__ __half g_Weth[128 * 128];
__device__ __half g_Webh[128 * 128];
__device__ __half g_Wallh[512 * 128];
__device__ __half g_tab[(size_t)TABN * 128];
__device__ __half g_vj[(size_t)Ee * Dd];   // CSR-ordered: slot-major
__device__ float  g_alpha[Ee * 2];         // CSR-ordered: [slot][head]
// CSR by dst
__device__ int    g_cnt[Nn];
__device__ int    g_rowstart[Nn];
__device__ int    g_cursor[Nn];
__device__ int    g_bsum[256];

__device__ __forceinline__ uint32_t smem_u32(const void* p) {
    uint32_t a;
    asm("{ .reg .u64 t; cvta.to.shared.u64 t, %1; cvt.u32.u64 %0, t; }" : "=r"(a) : "l"(p));
    return a;
}

__device__ __forceinline__ void ldsm_x4(uint32_t* r, uint32_t addr) {
    asm volatile("ldmatrix.sync.aligned.m8n8.x4.shared.b16 {%0,%1,%2,%3}, [%4];"
                 : "=r"(r[0]), "=r"(r[1]), "=r"(r[2]), "=r"(r[3]) : "r"(addr));
}

__device__ __forceinline__ void mma16816(float* c, const uint32_t* a, const uint32_t* b) {
    asm volatile("mma.sync.aligned.m16n8k16.row.col.f32.f16.f16.f32 "
                 "{%0,%1,%2,%3}, {%4,%5,%6,%7}, {%8,%9}, {%0,%1,%2,%3};"
                 : "+f"(c[0]), "+f"(c[1]), "+f"(c[2]), "+f"(c[3])
                 : "r"(a[0]), "r"(a[1]), "r"(a[2]), "r"(a[3]), "r"(b[0]), "r"(b[1]));
}

// ---------------- prep (vectorized x conversion) ----------------
__global__ void k_prep(const float* __restrict__ x, const float* __restrict__ We,
                       const float* __restrict__ Wq, const float* __restrict__ Wk,
                       const float* __restrict__ Wv, const float* __restrict__ Ws)
{
    int i = blockIdx.x * blockDim.x + threadIdx.x;
    if (i < Nn * Dd / 8) {
        const float4* xp = (const float4*)(x + (size_t)i * 8);
        float4 a = __ldcs(xp), b = __ldcs(xp + 1);
        __half2 h[4];
        h[0] = __floats2half2_rn(a.x, a.y); h[1] = __floats2half2_rn(a.z, a.w);
        h[2] = __floats2half2_rn(b.x, b.y); h[3] = __floats2half2_rn(b.z, b.w);
        ((uint4*)g_xh)[i] = *(uint4*)h;
    }
    if (i < 128 * 128) {
        int n = i >> 7, k = i & 127;
        g_Weth[i] = __float2half_rn(We[k * 128 + n]);
        g_Webh[i] = __float2half_rn(We[(k + 128) * 128 + n]);
    }
    if (i < 512 * 128) {
        int j = i >> 7, kk = i & 127;
        int m = j >> 7, n = j & 127;
        const float* W = (m == 0) ? Wq : (m == 1) ? Wk : (m == 2) ? Wv : Ws;
        g_Wallh[i] = __float2half_rn(W[kk * 128 + n]);
    }
    if (i < Nn) g_cnt[i] = 0;
}

// ---------------- CSR build ----------------
__global__ void k_hist(const int* __restrict__ ei) {
    int e = blockIdx.x * blockDim.x + threadIdx.x;
    if (e < Ee) atomicAdd(&g_cnt[ei[Ee + e]], 1);
}

__global__ void k_scan1() {
    __shared__ int s[256];
    int i = blockIdx.x * 256 + threadIdx.x;
    int c = (i < Nn) ? g_cnt[i] : 0;
    s[threadIdx.x] = c;
    __syncthreads();
    for (int off = 1; off < 256; off <<= 1) {
        int t = (threadIdx.x >= off) ? s[threadIdx.x - off] : 0;
        __syncthreads();
        s[threadIdx.x] += t;
        __syncthreads();
    }
    if (i < Nn) g_rowstart[i] = s[threadIdx.x] - c;
    if (threadIdx.x == 255) g_bsum[blockIdx.x] = s[255];
}

// merged scan2+final: each block reduces the block-sums below it, then applies
__global__ void k_final(int nb) {
    __shared__ int s[256];
    int bid = blockIdx.x, t = threadIdx.x;
    s[t] = (t < nb && t < bid) ? g_bsum[t] : 0;
    __syncthreads();
    for (int off = 128; off > 0; off >>= 1) {
        if (t < off) s[t] += s[t + off];
        __syncthreads();
    }
    int boff = s[0];
    int i = bid * 256 + t;
    if (i < Nn) {
        int r = g_rowstart[i] + boff;
        g_rowstart[i] = r;
        g_cursor[i] = r;
    }
}

// ---------------- table build ----------------
#define TB_B_OFF 34816
#define TB_WT    69632
#define TB_BT    70144
#define TB_SMEM  70656
#define TB_TILES (TABN / 128)

__global__ void __launch_bounds__(256, 2) k_table(const float* __restrict__ Wt,
                                                  const float* __restrict__ bt)
{
    extern __shared__ char sm[];
    uint32_t sbase = smem_u32(sm);
    int tid = threadIdx.x, w = tid >> 5, l = tid & 31;
    float* sWt = (float*)(sm + TB_WT);
    float* sBt = (float*)(sm + TB_BT);

    if (tid < 128) { sWt[tid] = Wt[tid]; sBt[tid] = bt[tid]; }
    for (int c = tid; c < 2048; c += 256) {
        int row = c >> 4, kc = c & 15;
        *(uint4*)(sm + TB_B_OFF + row * 272 + kc * 16) = ((const uint4*)g_Weth)[c];
    }

    int rg = w >> 1, cg = w & 1;
    for (int tile = blockIdx.x; tile < TB_TILES; tile += gridDim.x) {
        __syncthreads();
        for (int idx = tid; idx < 8192; idx += 256) {
            int row = idx >> 6, k2 = (idx & 63) * 2;
            float th = TH0 + (float)(tile * 128 + row) * HSTEP;
            float a0 = cosf(fmaf(th, sWt[k2],     sBt[k2]));
            float a1 = cosf(fmaf(th, sWt[k2 + 1], sBt[k2 + 1]));
            *(__half2*)(sm + row * 272 + k2 * 2) = __floats2half2_rn(a0, a1);
        }
        __syncthreads();

        float acc[2][8][4];
#pragma unroll
        for (int mi = 0; mi < 2; mi++)
#pragma unroll
            for (int nb = 0; nb < 8; nb++)
#pragma unroll
                for (int j = 0; j < 4; j++) acc[mi][nb][j] = 0.0f;

#pragma unroll
        for (int ks = 0; ks < 8; ks++) {
            uint32_t af[2][4];
#pragma unroll
            for (int mi = 0; mi < 2; mi++) {
                uint32_t addr = sbase + (uint32_t)(rg * 32 + mi * 16 + (l & 15)) * 272
                              + ks * 32 + (l >> 4) * 16;
                ldsm_x4(af[mi], addr);
            }
            uint32_t bf[8][2];
#pragma unroll
            for (int nbp = 0; nbp < 4; nbp++) {
                uint32_t r[4];
                int n = cg * 64 + nbp * 16 + (l & 7) + ((l >> 4) << 3);
                uint32_t addr = sbase + TB_B_OFF + (uint32_t)n * 272
                              + ks * 32 + ((l >> 3) & 1) * 16;
                ldsm_x4(r, addr);
                bf[nbp * 2][0] = r[0]; bf[nbp * 2][1] = r[1];
                bf[nbp * 2 + 1][0] = r[2]; bf[nbp * 2 + 1][1] = r[3];
            }
#pragma unroll
            for (int mi = 0; mi < 2; mi++)
#pragma unroll
                for (int nb = 0; nb < 8; nb++)
                    mma16816(acc[mi][nb], af[mi], bf[nb]);
        }

#pragma unroll
        for (int mi = 0; mi < 2; mi++) {
            int r0 = tile * 128 + rg * 32 + mi * 16 + (l >> 2);
#pragma unroll
            for (int nb = 0; nb < 8; nb++) {
                int col = cg * 64 + nb * 8 + 2 * (l & 3);
                *(__half2*)&g_tab[(size_t)r0 * 128 + col] =
                    __floats2half2_rn(acc[mi][nb][0], acc[mi][nb][1]);
                *(__half2*)&g_tab[(size_t)(r0 + 8) * 128 + col] =
                    __floats2half2_rn(acc[mi][nb][2], acc[mi][nb][3]);
            }
        }
    }
}

// ---------------- node GEMM: 2 matrices per CTA, A staged once ----------------
#define NODE_B_OFF 34816
#define NODE_SMEM  104448
#define N_TILES    391

__global__ void __launch_bounds__(256, 2) k_node_mma(
    const float* __restrict__ bq, const float* __restrict__ bk,
    const float* __restrict__ bv, const float* __restrict__ bs,
    float* __restrict__ out)
{
    extern __shared__ char sm[];
    uint32_t sbase = smem_u32(sm);
    int tid = threadIdx.x, w = tid >> 5, l = tid & 31;
    int m0 = blockIdx.y * 2;   // mats {m0, m0+1}

    // resident B0, B1
    for (int mi = 0; mi < 2; mi++) {
        const __half* Wsrc = g_Wallh + (size_t)(m0 + mi) * 128 * 128;
        for (int c = tid; c < 2048; c += 256) {
            int row = c >> 4, kc = c & 15;
            *(uint4*)(sm + NODE_B_OFF + mi * 34816 + row * 272 + kc * 16) = ((const uint4*)Wsrc)[c];
        }
    }

    int rg = w >> 1, cg = w & 1;
    for (int tile = blockIdx.x; tile < N_TILES; tile += gridDim.x) {
        int n0 = tile * 128;
        __syncthreads();
        for (int c = tid; c < 2048; c += 256) {
            int row = c >> 4, kc = c & 15;
            int nr = n0 + row;
            uint4 v = make_uint4(0, 0, 0, 0);
            if (nr < Nn) v = ((const uint4*)g_xh)[((size_t)nr * 128) / 8 + kc];
            *(uint4*)(sm + row * 272 + kc * 16) = v;
        }
        __syncthreads();

        for (int mm = 0; mm < 2; mm++) {
            int mat = m0 + mm;
            float acc[2][8][4];
#pragma unroll
            for (int mi = 0; mi < 2; mi++)
#pragma unroll
                for (int nb = 0; nb < 8; nb++)
#pragma unroll
                    for (int j = 0; j < 4; j++) acc[mi][nb][j] = 0.0f;

#pragma unroll
            for (int ks = 0; ks < 8; ks++) {
                uint32_t af[2][4];
#pragma unroll
                for (int mi = 0; mi < 2; mi++) {
                    uint32_t addr = sbase + (uint32_t)(rg * 32 + mi * 16 + (l & 15)) * 272
                                  + ks * 32 + (l >> 4) * 16;
                    ldsm_x4(af[mi], addr);
                }
                uint32_t bf[8][2];
#pragma unroll
                for (int nbp = 0; nbp < 4; nbp++) {
                    uint32_t r[4];
                    int n = cg * 64 + nbp * 16 + (l & 7) + ((l >> 4) << 3);
                    uint32_t addr = sbase + NODE_B_OFF + mm * 34816 + (uint32_t)n * 272
                                  + ks * 32 + ((l >> 3) & 1) * 16;
                    ldsm_x4(r, addr);
                    bf[nbp * 2][0] = r[0]; bf[nbp * 2][1] = r[1];
                    bf[nbp * 2 + 1][0] = r[2]; bf[nbp * 2 + 1][1] = r[3];
                }
#pragma unroll
                for (int mi = 0; mi < 2; mi++)
#pragma unroll
                    for (int nb = 0; nb < 8; nb++)
                        mma16816(acc[mi][nb], af[mi], bf[nb]);
            }

            const float* bias = (mat == 0) ? bq : (mat == 1) ? bk : (mat == 2) ? bv : bs;
#pragma unroll
            for (int mi = 0; mi < 2; mi++) {
                int r0 = n0 + rg * 32 + mi * 16 + (l >> 2);
#pragma unroll
                for (int nb = 0; nb < 8; nb++) {
                    int col = cg * 64 + nb * 8 + 2 * (l & 3);
                    float2 bi = *(const float2*)&bias[col];
                    if (mat == 3) {
                        if (r0 < Nn)
                            *(float2*)&out[(size_t)r0 * 128 + col] =
                                make_float2(acc[mi][nb][0] + bi.x, acc[mi][nb][1] + bi.y);
                        if (r0 + 8 < Nn)
                            *(float2*)&out[(size_t)(r0 + 8) * 128 + col] =
                                make_float2(acc[mi][nb][2] + bi.x, acc[mi][nb][3] + bi.y);
                    } else {
                        __half* dst = (mat == 0) ? g_qh : (mat == 1) ? g_kh : g_vh;
                        if (r0 < Nn)
                            *(__half2*)&dst[(size_t)r0 * 128 + col] =
                                __floats2half2_rn(acc[mi][nb][0] + bi.x, acc[mi][nb][1] + bi.y);
                        if (r0 + 8 < Nn)
                            *(__half2*)&dst[(size_t)(r0 + 8) * 128 + col] =
                                __floats2half2_rn(acc[mi][nb][2] + bi.x, acc[mi][nb][3] + bi.y);
                    }
                }
            }
        }
    }
}

// ---------------- edge GEMM: 512 threads, warp tile 32x32, self-claiming slots ----------------
#define E_B_OFF   34816
#define E_SRC     69632
#define E_DST     70144
#define E_RLT     70656
#define E_SLOT    71168
#define EDGE_SMEM 71680
#define E_TILES   (Ee / 128)

__global__ void __launch_bounds__(512, 2) k_edge_mma(
    const int*   __restrict__ ei,
    const float* __restrict__ last_update,
    const float* __restrict__ t,
    const float* __restrict__ msg)
{
    extern __shared__ char sm[];
    uint32_t sbase = smem_u32(sm);
    int tid = threadIdx.x, w = tid >> 5, l = tid & 31;

    int*   sSrc  = (int*)(sm + E_SRC);
    int*   sDst  = (int*)(sm + E_DST);
    float* sRlt  = (float*)(sm + E_RLT);
    int*   sSlot = (int*)(sm + E_SLOT);

    for (int c = tid; c < 2048; c += 512) {
        int row = c >> 4, kc = c & 15;
        *(uint4*)(sm + E_B_OFF + row * 272 + kc * 16) = ((const uint4*)g_Webh)[c];
    }

    int rg = w >> 2, cg = w & 3;
    for (int tile = blockIdx.x; tile < E_TILES; tile += gridDim.x) {
        __syncthreads();
        if (tid < 128) {
            int e = tile * 128 + tid;
            int s = ei[e];
            int d = ei[Ee + e];
            sSrc[tid]  = s;
            sDst[tid]  = d;
            sRlt[tid]  = last_update[s] - t[e];
            sSlot[tid] = atomicAdd(&g_cursor[d], 1);
        }
        for (int c = tid; c < 2048; c += 512) {
            int row = c >> 4, kc = c & 15;
            const float4* mp = (const float4*)(msg + (size_t)(tile * 128 + row) * 128 + kc * 8);
            float4 m0 = __ldcs(mp), m1 = __ldcs(mp + 1);
            __half2 h[4];
            h[0] = __floats2half2_rn(m0.x, m0.y); h[1] = __floats2half2_rn(m0.z, m0.w);
            h[2] = __floats2half2_rn(m1.x, m1.y); h[3] = __floats2half2_rn(m1.z, m1.w);
            *(uint4*)(sm + row * 272 + kc * 16) = *(uint4*)h;
        }
        __syncthreads();

        float acc[2][4][4];
#pragma unroll
        for (int mi = 0; mi < 2; mi++)
#pragma unroll
            for (int nb = 0; nb < 4; nb++)
#pragma unroll
                for (int j = 0; j < 4; j++) acc[mi][nb][j] = 0.0f;

#pragma unroll
        for (int ks = 0; ks < 8; ks++) {
            uint32_t af[2][4];
#pragma unroll
            for (int mi = 0; mi < 2; mi++) {
                uint32_t addr = sbase + (uint32_t)(rg * 32 + mi * 16 + (l & 15)) * 272
                              + ks * 32 + (l >> 4) * 16;
                ldsm_x4(af[mi], addr);
            }
            uint32_t bf[4][2];
#pragma unroll
            for (int nbp = 0; nbp < 2; nbp++) {
                uint32_t r[4];
                int n = cg * 32 + nbp * 16 + (l & 7) + ((l >> 4) << 3);
                uint32_t addr = sbase + E_B_OFF + (uint32_t)n * 272
                              + ks * 32 + ((l >> 3) & 1) * 16;
                ldsm_x4(r, addr);
                bf[nbp * 2][0] = r[0]; bf[nbp * 2][1] = r[1];
                bf[nbp * 2 + 1][0] = r[2]; bf[nbp * 2 + 1][1] = r[3];
            }
#pragma unroll
            for (int mi = 0; mi < 2; mi++)
#pragma unroll
                for (int nb = 0; nb < 4; nb++)
                    mma16816(acc[mi][nb], af[mi], bf[nb]);
        }
        __syncthreads();

#pragma unroll
        for (int mi = 0; mi < 2; mi++) {
            int r0 = rg * 32 + mi * 16 + (l >> 2);
#pragma unroll
            for (int nb = 0; nb < 4; nb++) {
                int col = cg * 32 + nb * 8 + 2 * (l & 3);
                *(__half2*)(sm + r0 * 272 + col * 2) =
                    __floats2half2_rn(acc[mi][nb][0], acc[mi][nb][1]);
                *(__half2*)(sm + (r0 + 8) * 272 + col * 2) =
                    __floats2half2_rn(acc[mi][nb][2], acc[mi][nb][3]);
            }
        }
        __syncthreads();

        // epilogue: 8 lanes per (edge, half) task; vj/alpha to CSR slot
        {
            int group = l >> 3, sub = l & 7;
#pragma unroll
            for (int it = 0; it < 4; it++) {
                int T = w * 16 + it * 4 + group;
                int el = T >> 1, hf = T & 1;
                int s = sSrc[el];
                int slot = sSlot[el];

                float f = (sRlt[el] - TH0) * TSCALE;
                int i0 = (int)f;
                i0 = max(0, min(i0, TABN - 2));
                float fr = f - (float)i0;

                int cb = hf * 64 + sub * 8;

                uint4 cu  = *(const uint4*)(sm + el * 272 + cb * 2);
                uint4 qu  = *(const uint4*)(g_qh + (size_t)sDst[el] * 128 + cb);
                uint4 ku  = *(const uint4*)(g_kh + (size_t)s * 128 + cb);
                uint4 vu  = *(const uint4*)(g_vh + (size_t)s * 128 + cb);
                uint4 g0u = *(const uint4*)(g_tab + (size_t)i0 * 128 + cb);
                uint4 g1u = *(const uint4*)(g_tab + (size_t)(i0 + 1) * 128 + cb);

                __half2* q2  = (__half2*)&qu;
                __half2* k2  = (__half2*)&ku;
                __half2* v2  = (__half2*)&vu;
                __half2* c2  = (__half2*)&cu;
                __half2* g02 = (__half2*)&g0u;
                __half2* g12 = (__half2*)&g1u;

                float dot = 0.0f;
                __half2 o2[4];
#pragma unroll
                for (int j = 0; j < 4; j++) {
                    float2 cf = __half22float2(c2[j]);
                    float2 ga = __half22float2(g02[j]);
                    float2 gb = __half22float2(g12[j]);
                    float ea = cf.x + ga.x + fr * (gb.x - ga.x);
                    float eb = cf.y + ga.y + fr * (gb.y - ga.y);
                    float2 qf = __half22float2(q2[j]);
                    float2 kf = __half22float2(k2[j]);
                    float2 vf = __half22float2(v2[j]);
                    dot = fmaf(qf.x, kf.x + ea, dot);
                    dot = fmaf(qf.y, kf.y + eb, dot);
                    o2[j] = __floats2half2_rn(vf.x + ea, vf.y + eb);
                }
                __stcs((uint4*)(g_vj + (size_t)slot * 128 + cb), *(uint4*)o2);

                dot += __shfl_xor_sync(0xffffffffu, dot, 1);
                dot += __shfl_xor_sync(0xffffffffu, dot, 2);
                dot += __shfl_xor_sync(0xffffffffu, dot, 4);
                if (sub == 0) g_alpha[slot * 2 + hf] = dot * 0.125f;
            }
        }
    }
}

// ---------------- CSR softmax + aggregation: pure streaming ----------------
__global__ void __launch_bounds__(256) k_aggcsr(float* __restrict__ out)
{
    int tid = blockIdx.x * blockDim.x + threadIdx.x;
    int g = tid >> 4, sub = tid & 15;
    if (g >= Nn) return;
    int beg = g_rowstart[g];
    int end = beg + g_cnt[g];
    if (end <= beg) return;

    float m0 = -INFINITY, m1 = -INFINITY;
    for (int p = beg + sub; p < end; p += 16) {
        float2 al = *(const float2*)&g_alpha[p * 2];
        m0 = fmaxf(m0, al.x);
        m1 = fmaxf(m1, al.y);
    }
#pragma unroll
    for (int s = 1; s < 16; s <<= 1) {
        m0 = fmaxf(m0, __shfl_xor_sync(0xffffffffu, m0, s, 16));
        m1 = fmaxf(m1, __shfl_xor_sync(0xffffffffu, m1, s, 16));
    }

    float ex0[4], ex1[4];
    float s0 = 0.0f, s1 = 0.0f;
    int nch = min((end - beg + 15) >> 4, 4);
#pragma unroll
    for (int c = 0; c < 4; c++) { ex0[c] = 0.0f; ex1[c] = 0.0f; }
    for (int c = 0; c < nch; c++) {
        int p = beg + c * 16 + sub;
        float a0 = 0.0f, a1 = 0.0f;
        if (p < end) {
            float2 al = *(const float2*)&g_alpha[p * 2];
            a0 = expf(al.x - m0);
            a1 = expf(al.y - m1);
        }
        ex0[c] = a0; ex1[c] = a1;
        s0 += a0; s1 += a1;
    }
    for (int p = beg + 64 + sub; p < end; p += 16) {
        float2 al = *(const float2*)&g_alpha[p * 2];
        s0 += expf(al.x - m0);
        s1 += expf(al.y - m1);
    }
#pragma unroll
    for (int s = 1; s < 16; s <<= 1) {
        s0 += __shfl_xor_sync(0xffffffffu, s0, s, 16);
        s1 += __shfl_xor_sync(0xffffffffu, s1, s, 16);
    }
    float inv = (sub < 8) ? (1.0f / s0) : (1.0f / s1);

    float acc[8];
#pragma unroll
    for (int j = 0; j < 8; j++) acc[j] = 0.0f;

    for (int c = 0; c < nch; c++) {
#pragma unroll
        for (int j = 0; j < 16; j++) {
            int p = beg + c * 16 + j;
            float A = __shfl_sync(0xffffffffu, ex0[c], j, 16);
            float B = __shfl_sync(0xffffffffu, ex1[c], j, 16);
            if (p >= end) break;
            float wv = ((sub < 8) ? A : B) * inv;
            uint4 vju = __ldcs((const uint4*)(g_vj + (size_t)p * 128 + sub * 8));
            __half2* v2 = (__half2*)&vju;
#pragma unroll
            for (int q = 0; q < 4; q++) {
                float2 vf = __half22float2(v2[q]);
                acc[q * 2]     = fmaf(wv, vf.x, acc[q * 2]);
                acc[q * 2 + 1] = fmaf(wv, vf.y, acc[q * 2 + 1]);
            }
        }
    }
    for (int p = beg + 64; p < end; p++) {
        float2 al = *(const float2*)&g_alpha[p * 2];
        float wv = ((sub < 8) ? expf(al.x - m0) : expf(al.y - m1)) * inv;
        uint4 vju = __ldcs((const uint4*)(g_vj + (size_t)p * 128 + sub * 8));
        __half2* v2 = (__half2*)&vju;
#pragma unroll
        for (int q = 0; q < 4; q++) {
            float2 vf = __half22float2(v2[q]);
            acc[q * 2]     = fmaf(wv, vf.x, acc[q * 2]);
            acc[q * 2 + 1] = fmaf(wv, vf.y, acc[q * 2 + 1]);
        }
    }

    float4* op = (float4*)&out[(size_t)g * 128 + sub * 8];
    float4 o0 = op[0], o1 = op[1];
    o0.x += acc[0]; o0.y += acc[1]; o0.z += acc[2]; o0.w += acc[3];
    o1.x += acc[4]; o1.y += acc[5]; o1.z += acc[6]; o1.w += acc[7];
    op[0] = o0; op[1] = o1;
}

// ---------------- launch ----------------
extern "C" void kernel_launch(void* const* d_in, const int* in_sizes, int n_in,
                              void* d_out, int out_size)
{
    const float* x           = (const float*)d_in[0];
    const float* last_update = (const float*)d_in[1];
    const int*   ei          = (const int*)  d_in[2];
    const float* t           = (const float*)d_in[3];
    const float* msg         = (const float*)d_in[4];
    const float* Wt          = (const float*)d_in[5];
    const float* bt          = (const float*)d_in[6];
    const float* Wq          = (const float*)d_in[7];
    const float* bq          = (const float*)d_in[8];
    const float* Wk          = (const float*)d_in[9];
    const float* bk          = (const float*)d_in[10];
    const float* Wv          = (const float*)d_in[11];
    const float* bv          = (const float*)d_in[12];
    const float* We          = (const float*)d_in[13];
    const float* Wskip       = (const float*)d_in[14];
    const float* bskip       = (const float*)d_in[15];
    float* out = (float*)d_out;

    cudaFuncSetAttribute(k_table,    cudaFuncAttributeMaxDynamicSharedMemorySize, TB_SMEM);
    cudaFuncSetAttribute(k_node_mma, cudaFuncAttributeMaxDynamicSharedMemorySize, NODE_SMEM);
    cudaFuncSetAttribute(k_edge_mma, cudaFuncAttributeMaxDynamicSharedMemorySize, EDGE_SMEM);

    const int NB1 = (Nn + 255) / 256;

    k_prep<<<(Nn * Dd / 8 + 255) / 256, 256>>>(x, We, Wq, Wk, Wv, Wskip);

    k_hist<<<(Ee + 255) / 256, 256>>>(ei);
    k_scan1<<<NB1, 256>>>();
    k_final<<<NB1, 256>>>(NB1);

    k_table<<<256, 256, TB_SMEM>>>(Wt, bt);

    dim3 gn(74, 2);
    k_node_mma<<<gn, 256, NODE_SMEM>>>(bq, bk, bv, bskip, out);

    k_edge_mma<<<296, 512, EDGE_SMEM>>>(ei, last_update, t, msg);

    k_aggcsr<<<(Nn * 16 + 255) / 256, 256>>>(out);
}

// round 16
// speedup vs baseline: 1.3800x; 1.3800x over previous
#include <cuda_runtime.h>
#include <cuda_fp16.h>
#include <cstdint>
#include <math.h>

#define Nn 50000
#define Ee 800000
#define Dd 128

#define TABN 32768
#define TH0  (-1000.0f)
#define HSTEP   (2000.0f / (TABN - 1))
#define TSCALE  ((TABN - 1) / 2000.0f)

// ---------------- scratch (static device globals; no allocation) ----------------
__device__ __half g_xh[(size_t)Nn * Dd];
__device__ __half g_qh[(size_t)Nn * Dd];
__device__ __half g_kh[(size_t)Nn * Dd];
__device__ __half g_vh[(size_t)Nn * Dd];
__device__ __half g_Weth[128 * 128];
__device__ __half g_Webh[128 * 128];
__device__ __half g_Wallh[512 * 128];
__device__ __half g_tab[(size_t)TABN * 128];
__device__ __half g_vj[(size_t)Ee * Dd];   // CSR-ordered: slot-major
__device__ float  g_alpha[Ee * 2];         // CSR-ordered: [slot][head]
// CSR by dst
__device__ int    g_cnt[Nn];
__device__ int    g_rowstart[Nn];
__device__ int    g_cursor[Nn];
__device__ int    g_bsum[256];

__device__ __forceinline__ uint32_t smem_u32(const void* p) {
    uint32_t a;
    asm("{ .reg .u64 t; cvta.to.shared.u64 t, %1; cvt.u32.u64 %0, t; }" : "=r"(a) : "l"(p));
    return a;
}

__device__ __forceinline__ void ldsm_x4(uint32_t* r, uint32_t addr) {
    asm volatile("ldmatrix.sync.aligned.m8n8.x4.shared.b16 {%0,%1,%2,%3}, [%4];"
                 : "=r"(r[0]), "=r"(r[1]), "=r"(r[2]), "=r"(r[3]) : "r"(addr));
}

__device__ __forceinline__ void mma16816(float* c, const uint32_t* a, const uint32_t* b) {
    asm volatile("mma.sync.aligned.m16n8k16.row.col.f32.f16.f16.f32 "
                 "{%0,%1,%2,%3}, {%4,%5,%6,%7}, {%8,%9}, {%0,%1,%2,%3};"
                 : "+f"(c[0]), "+f"(c[1]), "+f"(c[2]), "+f"(c[3])
                 : "r"(a[0]), "r"(a[1]), "r"(a[2]), "r"(a[3]), "r"(b[0]), "r"(b[1]));
}

// ---------------- prep (vectorized x conversion) ----------------
__global__ void k_prep(const float* __restrict__ x, const float* __restrict__ We,
                       const float* __restrict__ Wq, const float* __restrict__ Wk,
                       const float* __restrict__ Wv, const float* __restrict__ Ws)
{
    int i = blockIdx.x * blockDim.x + threadIdx.x;
    if (i < Nn * Dd / 8) {
        const float4* xp = (const float4*)(x + (size_t)i * 8);
        float4 a = __ldcs(xp), b = __ldcs(xp + 1);
        __half2 h[4];
        h[0] = __floats2half2_rn(a.x, a.y); h[1] = __floats2half2_rn(a.z, a.w);
        h[2] = __floats2half2_rn(b.x, b.y); h[3] = __floats2half2_rn(b.z, b.w);
        ((uint4*)g_xh)[i] = *(uint4*)h;
    }
    if (i < 128 * 128) {
        int n = i >> 7, k = i & 127;
        g_Weth[i] = __float2half_rn(We[k * 128 + n]);
        g_Webh[i] = __float2half_rn(We[(k + 128) * 128 + n]);
    }
    if (i < 512 * 128) {
        int j = i >> 7, kk = i & 127;
        int m = j >> 7, n = j & 127;
        const float* W = (m == 0) ? Wq : (m == 1) ? Wk : (m == 2) ? Wv : Ws;
        g_Wallh[i] = __float2half_rn(W[kk * 128 + n]);
    }
    if (i < Nn) g_cnt[i] = 0;
}

// ---------------- CSR build ----------------
__global__ void k_hist(const int* __restrict__ ei) {
    int e = blockIdx.x * blockDim.x + threadIdx.x;
    if (e < Ee) atomicAdd(&g_cnt[ei[Ee + e]], 1);
}

__global__ void k_scan1() {
    __shared__ int s[256];
    int i = blockIdx.x * 256 + threadIdx.x;
    int c = (i < Nn) ? g_cnt[i] : 0;
    s[threadIdx.x] = c;
    __syncthreads();
    for (int off = 1; off < 256; off <<= 1) {
        int t = (threadIdx.x >= off) ? s[threadIdx.x - off] : 0;
        __syncthreads();
        s[threadIdx.x] += t;
        __syncthreads();
    }
    if (i < Nn) g_rowstart[i] = s[threadIdx.x] - c;
    if (threadIdx.x == 255) g_bsum[blockIdx.x] = s[255];
}

// merged scan2+final: each block reduces the block-sums below it, then applies
__global__ void k_final(int nb) {
    __shared__ int s[256];
    int bid = blockIdx.x, t = threadIdx.x;
    s[t] = (t < nb && t < bid) ? g_bsum[t] : 0;
    __syncthreads();
    for (int off = 128; off > 0; off >>= 1) {
        if (t < off) s[t] += s[t + off];
        __syncthreads();
    }
    int boff = s[0];
    int i = bid * 256 + t;
    if (i < Nn) {
        int r = g_rowstart[i] + boff;
        g_rowstart[i] = r;
        g_cursor[i] = r;
    }
}

// ---------------- table build ----------------
#define TB_B_OFF 34816
#define TB_WT    69632
#define TB_BT    70144
#define TB_SMEM  70656
#define TB_TILES (TABN / 128)

__global__ void __launch_bounds__(256, 2) k_table(const float* __restrict__ Wt,
                                                  const float* __restrict__ bt)
{
    extern __shared__ char sm[];
    uint32_t sbase = smem_u32(sm);
    int tid = threadIdx.x, w = tid >> 5, l = tid & 31;
    float* sWt = (float*)(sm + TB_WT);
    float* sBt = (float*)(sm + TB_BT);

    if (tid < 128) { sWt[tid] = Wt[tid]; sBt[tid] = bt[tid]; }
    for (int c = tid; c < 2048; c += 256) {
        int row = c >> 4, kc = c & 15;
        *(uint4*)(sm + TB_B_OFF + row * 272 + kc * 16) = ((const uint4*)g_Weth)[c];
    }

    int rg = w >> 1, cg = w & 1;
    for (int tile = blockIdx.x; tile < TB_TILES; tile += gridDim.x) {
        __syncthreads();
        for (int idx = tid; idx < 8192; idx += 256) {
            int row = idx >> 6, k2 = (idx & 63) * 2;
            float th = TH0 + (float)(tile * 128 + row) * HSTEP;
            float a0 = cosf(fmaf(th, sWt[k2],     sBt[k2]));
            float a1 = cosf(fmaf(th, sWt[k2 + 1], sBt[k2 + 1]));
            *(__half2*)(sm + row * 272 + k2 * 2) = __floats2half2_rn(a0, a1);
        }
        __syncthreads();

        float acc[2][8][4];
#pragma unroll
        for (int mi = 0; mi < 2; mi++)
#pragma unroll
            for (int nb = 0; nb < 8; nb++)
#pragma unroll
                for (int j = 0; j < 4; j++) acc[mi][nb][j] = 0.0f;

#pragma unroll
        for (int ks = 0; ks < 8; ks++) {
            uint32_t af[2][4];
#pragma unroll
            for (int mi = 0; mi < 2; mi++) {
                uint32_t addr = sbase + (uint32_t)(rg * 32 + mi * 16 + (l & 15)) * 272
                              + ks * 32 + (l >> 4) * 16;
                ldsm_x4(af[mi], addr);
            }
            uint32_t bf[8][2];
#pragma unroll
            for (int nbp = 0; nbp < 4; nbp++) {
                uint32_t r[4];
                int n = cg * 64 + nbp * 16 + (l & 7) + ((l >> 4) << 3);
                uint32_t addr = sbase + TB_B_OFF + (uint32_t)n * 272
                              + ks * 32 + ((l >> 3) & 1) * 16;
                ldsm_x4(r, addr);
                bf[nbp * 2][0] = r[0]; bf[nbp * 2][1] = r[1];
                bf[nbp * 2 + 1][0] = r[2]; bf[nbp * 2 + 1][1] = r[3];
            }
#pragma unroll
            for (int mi = 0; mi < 2; mi++)
#pragma unroll
                for (int nb = 0; nb < 8; nb++)
                    mma16816(acc[mi][nb], af[mi], bf[nb]);
        }

#pragma unroll
        for (int mi = 0; mi < 2; mi++) {
            int r0 = tile * 128 + rg * 32 + mi * 16 + (l >> 2);
#pragma unroll
            for (int nb = 0; nb < 8; nb++) {
                int col = cg * 64 + nb * 8 + 2 * (l & 3);
                *(__half2*)&g_tab[(size_t)r0 * 128 + col] =
                    __floats2half2_rn(acc[mi][nb][0], acc[mi][nb][1]);
                *(__half2*)&g_tab[(size_t)(r0 + 8) * 128 + col] =
                    __floats2half2_rn(acc[mi][nb][2], acc[mi][nb][3]);
            }
        }
    }
}

// ---------------- node GEMM (R14 config: one matrix per grid.y slice) ----------------
#define NODE_B_OFF 34816
#define NODE_SMEM  69632
#define N_TILES    391

__global__ void __launch_bounds__(256, 2) k_node_mma(
    const float* __restrict__ bq, const float* __restrict__ bk,
    const float* __restrict__ bv, const float* __restrict__ bs,
    float* __restrict__ out)
{
    extern __shared__ char sm[];
    uint32_t sbase = smem_u32(sm);
    int tid = threadIdx.x, w = tid >> 5, l = tid & 31;
    int mat = blockIdx.y;

    const __half* Wsrc = g_Wallh + (size_t)mat * 128 * 128;
    for (int c = tid; c < 2048; c += 256) {
        int row = c >> 4, kc = c & 15;
        *(uint4*)(sm + NODE_B_OFF + row * 272 + kc * 16) = ((const uint4*)Wsrc)[c];
    }

    int rg = w >> 1, cg = w & 1;
    for (int tile = blockIdx.x; tile < N_TILES; tile += gridDim.x) {
        int n0 = tile * 128;
        __syncthreads();
        for (int c = tid; c < 2048; c += 256) {
            int row = c >> 4, kc = c & 15;
            int nr = n0 + row;
            uint4 v = make_uint4(0, 0, 0, 0);
            if (nr < Nn) v = ((const uint4*)g_xh)[((size_t)nr * 128) / 8 + kc];
            *(uint4*)(sm + row * 272 + kc * 16) = v;
        }
        __syncthreads();

        float acc[2][8][4];
#pragma unroll
        for (int mi = 0; mi < 2; mi++)
#pragma unroll
            for (int nb = 0; nb < 8; nb++)
#pragma unroll
                for (int j = 0; j < 4; j++) acc[mi][nb][j] = 0.0f;

#pragma unroll
        for (int ks = 0; ks < 8; ks++) {
            uint32_t af[2][4];
#pragma unroll
            for (int mi = 0; mi < 2; mi++) {
                uint32_t addr = sbase + (uint32_t)(rg * 32 + mi * 16 + (l & 15)) * 272
                              + ks * 32 + (l >> 4) * 16;
                ldsm_x4(af[mi], addr);
            }
            uint32_t bf[8][2];
#pragma unroll
            for (int nbp = 0; nbp < 4; nbp++) {
                uint32_t r[4];
                int n = cg * 64 + nbp * 16 + (l & 7) + ((l >> 4) << 3);
                uint32_t addr = sbase + NODE_B_OFF + (uint32_t)n * 272
                              + ks * 32 + ((l >> 3) & 1) * 16;
                ldsm_x4(r, addr);
                bf[nbp * 2][0] = r[0]; bf[nbp * 2][1] = r[1];
                bf[nbp * 2 + 1][0] = r[2]; bf[nbp * 2 + 1][1] = r[3];
            }
#pragma unroll
            for (int mi = 0; mi < 2; mi++)
#pragma unroll
                for (int nb = 0; nb < 8; nb++)
                    mma16816(acc[mi][nb], af[mi], bf[nb]);
        }

        const float* bias = (mat == 0) ? bq : (mat == 1) ? bk : (mat == 2) ? bv : bs;
#pragma unroll
        for (int mi = 0; mi < 2; mi++) {
            int r0 = n0 + rg * 32 + mi * 16 + (l >> 2);
#pragma unroll
            for (int nb = 0; nb < 8; nb++) {
                int col = cg * 64 + nb * 8 + 2 * (l & 3);
                float2 bi = *(const float2*)&bias[col];
                if (mat == 3) {
                    if (r0 < Nn)
                        *(float2*)&out[(size_t)r0 * 128 + col] =
                            make_float2(acc[mi][nb][0] + bi.x, acc[mi][nb][1] + bi.y);
                    if (r0 + 8 < Nn)
                        *(float2*)&out[(size_t)(r0 + 8) * 128 + col] =
                            make_float2(acc[mi][nb][2] + bi.x, acc[mi][nb][3] + bi.y);
                } else {
                    __half* dst = (mat == 0) ? g_qh : (mat == 1) ? g_kh : g_vh;
                    if (r0 < Nn)
                        *(__half2*)&dst[(size_t)r0 * 128 + col] =
                            __floats2half2_rn(acc[mi][nb][0] + bi.x, acc[mi][nb][1] + bi.y);
                    if (r0 + 8 < Nn)
                        *(__half2*)&dst[(size_t)(r0 + 8) * 128 + col] =
                            __floats2half2_rn(acc[mi][nb][2] + bi.x, acc[mi][nb][3] + bi.y);
                }
            }
        }
    }
}

// ---------------- edge GEMM: 512 threads, warp tile 32x32, self-claiming slots ----------------
#define E_B_OFF   34816
#define E_SRC     69632
#define E_DST     70144
#define E_RLT     70656
#define E_SLOT    71168
#define EDGE_SMEM 71680
#define E_TILES   (Ee / 128)

__global__ void __launch_bounds__(512, 2) k_edge_mma(
    const int*   __restrict__ ei,
    const float* __restrict__ last_update,
    const float* __restrict__ t,
    const float* __restrict__ msg)
{
    extern __shared__ char sm[];
    uint32_t sbase = smem_u32(sm);
    int tid = threadIdx.x, w = tid >> 5, l = tid & 31;

    int*   sSrc  = (int*)(sm + E_SRC);
    int*   sDst  = (int*)(sm + E_DST);
    float* sRlt  = (float*)(sm + E_RLT);
    int*   sSlot = (int*)(sm + E_SLOT);

    for (int c = tid; c < 2048; c += 512) {
        int row = c >> 4, kc = c & 15;
        *(uint4*)(sm + E_B_OFF + row * 272 + kc * 16) = ((const uint4*)g_Webh)[c];
    }

    int rg = w >> 2, cg = w & 3;
    for (int tile = blockIdx.x; tile < E_TILES; tile += gridDim.x) {
        __syncthreads();
        if (tid < 128) {
            int e = tile * 128 + tid;
            int s = ei[e];
            int d = ei[Ee + e];
            sSrc[tid]  = s;
            sDst[tid]  = d;
            sRlt[tid]  = last_update[s] - t[e];
            sSlot[tid] = atomicAdd(&g_cursor[d], 1);
        }
        for (int c = tid; c < 2048; c += 512) {
            int row = c >> 4, kc = c & 15;
            const float4* mp = (const float4*)(msg + (size_t)(tile * 128 + row) * 128 + kc * 8);
            float4 m0 = __ldcs(mp), m1 = __ldcs(mp + 1);
            __half2 h[4];
            h[0] = __floats2half2_rn(m0.x, m0.y); h[1] = __floats2half2_rn(m0.z, m0.w);
            h[2] = __floats2half2_rn(m1.x, m1.y); h[3] = __floats2half2_rn(m1.z, m1.w);
            *(uint4*)(sm + row * 272 + kc * 16) = *(uint4*)h;
        }
        __syncthreads();

        float acc[2][4][4];
#pragma unroll
        for (int mi = 0; mi < 2; mi++)
#pragma unroll
            for (int nb = 0; nb < 4; nb++)
#pragma unroll
                for (int j = 0; j < 4; j++) acc[mi][nb][j] = 0.0f;

#pragma unroll
        for (int ks = 0; ks < 8; ks++) {
            uint32_t af[2][4];
#pragma unroll
            for (int mi = 0; mi < 2; mi++) {
                uint32_t addr = sbase + (uint32_t)(rg * 32 + mi * 16 + (l & 15)) * 272
                              + ks * 32 + (l >> 4) * 16;
                ldsm_x4(af[mi], addr);
            }
            uint32_t bf[4][2];
#pragma unroll
            for (int nbp = 0; nbp < 2; nbp++) {
                uint32_t r[4];
                int n = cg * 32 + nbp * 16 + (l & 7) + ((l >> 4) << 3);
                uint32_t addr = sbase + E_B_OFF + (uint32_t)n * 272
                              + ks * 32 + ((l >> 3) & 1) * 16;
                ldsm_x4(r, addr);
                bf[nbp * 2][0] = r[0]; bf[nbp * 2][1] = r[1];
                bf[nbp * 2 + 1][0] = r[2]; bf[nbp * 2 + 1][1] = r[3];
            }
#pragma unroll
            for (int mi = 0; mi < 2; mi++)
#pragma unroll
                for (int nb = 0; nb < 4; nb++)
                    mma16816(acc[mi][nb], af[mi], bf[nb]);
        }
        __syncthreads();

#pragma unroll
        for (int mi = 0; mi < 2; mi++) {
            int r0 = rg * 32 + mi * 16 + (l >> 2);
#pragma unroll
            for (int nb = 0; nb < 4; nb++) {
                int col = cg * 32 + nb * 8 + 2 * (l & 3);
                *(__half2*)(sm + r0 * 272 + col * 2) =
                    __floats2half2_rn(acc[mi][nb][0], acc[mi][nb][1]);
                *(__half2*)(sm + (r0 + 8) * 272 + col * 2) =
                    __floats2half2_rn(acc[mi][nb][2], acc[mi][nb][3]);
            }
        }
        __syncthreads();

        // epilogue: 8 lanes per (edge, half) task; vj/alpha to CSR slot
        {
            int group = l >> 3, sub = l & 7;
#pragma unroll
            for (int it = 0; it < 4; it++) {
                int T = w * 16 + it * 4 + group;
                int el = T >> 1, hf = T & 1;
                int s = sSrc[el];
                int slot = sSlot[el];

                float f = (sRlt[el] - TH0) * TSCALE;
                int i0 = (int)f;
                i0 = max(0, min(i0, TABN - 2));
                float fr = f - (float)i0;

                int cb = hf * 64 + sub * 8;

                uint4 cu  = *(const uint4*)(sm + el * 272 + cb * 2);
                uint4 qu  = *(const uint4*)(g_qh + (size_t)sDst[el] * 128 + cb);
                uint4 ku  = *(const uint4*)(g_kh + (size_t)s * 128 + cb);
                uint4 vu  = *(const uint4*)(g_vh + (size_t)s * 128 + cb);
                uint4 g0u = *(const uint4*)(g_tab + (size_t)i0 * 128 + cb);
                uint4 g1u = *(const uint4*)(g_tab + (size_t)(i0 + 1) * 128 + cb);

                __half2* q2  = (__half2*)&qu;
                __half2* k2  = (__half2*)&ku;
                __half2* v2  = (__half2*)&vu;
                __half2* c2  = (__half2*)&cu;
                __half2* g02 = (__half2*)&g0u;
                __half2* g12 = (__half2*)&g1u;

                float dot = 0.0f;
                __half2 o2[4];
#pragma unroll
                for (int j = 0; j < 4; j++) {
                    float2 cf = __half22float2(c2[j]);
                    float2 ga = __half22float2(g02[j]);
                    float2 gb = __half22float2(g12[j]);
                    float ea = cf.x + ga.x + fr * (gb.x - ga.x);
                    float eb = cf.y + ga.y + fr * (gb.y - ga.y);
                    float2 qf = __half22float2(q2[j]);
                    float2 kf = __half22float2(k2[j]);
                    float2 vf = __half22float2(v2[j]);
                    dot = fmaf(qf.x, kf.x + ea, dot);
                    dot = fmaf(qf.y, kf.y + eb, dot);
                    o2[j] = __floats2half2_rn(vf.x + ea, vf.y + eb);
                }
                __stcs((uint4*)(g_vj + (size_t)slot * 128 + cb), *(uint4*)o2);

                dot += __shfl_xor_sync(0xffffffffu, dot, 1);
                dot += __shfl_xor_sync(0xffffffffu, dot, 2);
                dot += __shfl_xor_sync(0xffffffffu, dot, 4);
                if (sub == 0) g_alpha[slot * 2 + hf] = dot * 0.125f;
            }
        }
    }
}

// ---------------- CSR softmax + aggregation: pure streaming ----------------
__global__ void __launch_bounds__(256) k_aggcsr(float* __restrict__ out)
{
    int tid = blockIdx.x * blockDim.x + threadIdx.x;
    int g = tid >> 4, sub = tid & 15;
    if (g >= Nn) return;
    int beg = g_rowstart[g];
    int end = beg + g_cnt[g];
    if (end <= beg) return;

    float m0 = -INFINITY, m1 = -INFINITY;
    for (int p = beg + sub; p < end; p += 16) {
        float2 al = *(const float2*)&g_alpha[p * 2];
        m0 = fmaxf(m0, al.x);
        m1 = fmaxf(m1, al.y);
    }
#pragma unroll
    for (int s = 1; s < 16; s <<= 1) {
        m0 = fmaxf(m0, __shfl_xor_sync(0xffffffffu, m0, s, 16));
        m1 = fmaxf(m1, __shfl_xor_sync(0xffffffffu, m1, s, 16));
    }

    float ex0[4], ex1[4];
    float s0 = 0.0f, s1 = 0.0f;
    int nch = min((end - beg + 15) >> 4, 4);
#pragma unroll
    for (int c = 0; c < 4; c++) { ex0[c] = 0.0f; ex1[c] = 0.0f; }
    for (int c = 0; c < nch; c++) {
        int p = beg + c * 16 + sub;
        float a0 = 0.0f, a1 = 0.0f;
        if (p < end) {
            float2 al = *(const float2*)&g_alpha[p * 2];
            a0 = expf(al.x - m0);
            a1 = expf(al.y - m1);
        }
        ex0[c] = a0; ex1[c] = a1;
        s0 += a0; s1 += a1;
    }
    for (int p = beg + 64 + sub; p < end; p += 16) {
        float2 al = *(const float2*)&g_alpha[p * 2];
        s0 += expf(al.x - m0);
        s1 += expf(al.y - m1);
    }
#pragma unroll
    for (int s = 1; s < 16; s <<= 1) {
        s0 += __shfl_xor_sync(0xffffffffu, s0, s, 16);
        s1 += __shfl_xor_sync(0xffffffffu, s1, s, 16);
    }
    float inv = (sub < 8) ? (1.0f / s0) : (1.0f / s1);

    float acc[8];
#pragma unroll
    for (int j = 0; j < 8; j++) acc[j] = 0.0f;

    for (int c = 0; c < nch; c++) {
#pragma unroll
        for (int j = 0; j < 16; j++) {
            int p = beg + c * 16 + j;
            float A = __shfl_sync(0xffffffffu, ex0[c], j, 16);
            float B = __shfl_sync(0xffffffffu, ex1[c], j, 16);
            if (p >= end) break;
            float wv = ((sub < 8) ? A : B) * inv;
            uint4 vju = __ldcs((const uint4*)(g_vj + (size_t)p * 128 + sub * 8));
            __half2* v2 = (__half2*)&vju;
#pragma unroll
            for (int q = 0; q < 4; q++) {
                float2 vf = __half22float2(v2[q]);
                acc[q * 2]     = fmaf(wv, vf.x, acc[q * 2]);
                acc[q * 2 + 1] = fmaf(wv, vf.y, acc[q * 2 + 1]);
            }
        }
    }
    for (int p = beg + 64; p < end; p++) {
        float2 al = *(const float2*)&g_alpha[p * 2];
        float wv = ((sub < 8) ? expf(al.x - m0) : expf(al.y - m1)) * inv;
        uint4 vju = __ldcs((const uint4*)(g_vj + (size_t)p * 128 + sub * 8));
        __half2* v2 = (__half2*)&vju;
#pragma unroll
        for (int q = 0; q < 4; q++) {
            float2 vf = __half22float2(v2[q]);
            acc[q * 2]     = fmaf(wv, vf.x, acc[q * 2]);
            acc[q * 2 + 1] = fmaf(wv, vf.y, acc[q * 2 + 1]);
        }
    }

    float4* op = (float4*)&out[(size_t)g * 128 + sub * 8];
    float4 o0 = op[0], o1 = op[1];
    o0.x += acc[0]; o0.y += acc[1]; o0.z += acc[2]; o0.w += acc[3];
    o1.x += acc[4]; o1.y += acc[5]; o1.z += acc[6]; o1.w += acc[7];
    op[0] = o0; op[1] = o1;
}

// ---------------- launch ----------------
extern "C" void kernel_launch(void* const* d_in, const int* in_sizes, int n_in,
                              void* d_out, int out_size)
{
    const float* x           = (const float*)d_in[0];
    const float* last_update = (const float*)d_in[1];
    const int*   ei          = (const int*)  d_in[2];
    const float* t           = (const float*)d_in[3];
    const float* msg         = (const float*)d_in[4];
    const float* Wt          = (const float*)d_in[5];
    const float* bt          = (const float*)d_in[6];
    const float* Wq          = (const float*)d_in[7];
    const float* bq          = (const float*)d_in[8];
    const float* Wk          = (const float*)d_in[9];
    const float* bk          = (const float*)d_in[10];
    const float* Wv          = (const float*)d_in[11];
    const float* bv          = (const float*)d_in[12];
    const float* We          = (const float*)d_in[13];
    const float* Wskip       = (const float*)d_in[14];
    const float* bskip       = (const float*)d_in[15];
    float* out = (float*)d_out;

    cudaFuncSetAttribute(k_table,    cudaFuncAttributeMaxDynamicSharedMemorySize, TB_SMEM);
    cudaFuncSetAttribute(k_node_mma, cudaFuncAttributeMaxDynamicSharedMemorySize, NODE_SMEM);
    cudaFuncSetAttribute(k_edge_mma, cudaFuncAttributeMaxDynamicSharedMemorySize, EDGE_SMEM);

    const int NB1 = (Nn + 255) / 256;

    k_prep<<<(Nn * Dd / 8 + 255) / 256, 256>>>(x, We, Wq, Wk, Wv, Wskip);

    k_hist<<<(Ee + 255) / 256, 256>>>(ei);
    k_scan1<<<NB1, 256>>>();
    k_final<<<NB1, 256>>>(NB1);

    k_table<<<256, 256, TB_SMEM>>>(Wt, bt);

    dim3 gn(74, 4);
    k_node_mma<<<gn, 256, NODE_SMEM>>>(bq, bk, bv, bskip, out);

    k_edge_mma<<<296, 512, EDGE_SMEM>>>(ei, last_update, t, msg);

    k_aggcsr<<<(Nn * 16 + 255) / 256, 256>>>(out);
}